// round 13
// baseline (speedup 1.0000x reference)
#include <cuda_runtime.h>
#include <cstdint>

#define BB 32
#define SQ 128
#define EE 512
#define FF 2048

__device__ float g_H[(size_t)SQ * BB * FF];  // [s][b][f]
__device__ int   g_done[SQ];

#define STG    35328          // A 32x80=2560 + B 16x2048=32768
#define NSTAGE 6
#define SMB    (NSTAGE * STG) // 211968
#define LAG    30
#define NBLK   640            // 512 gemm1 + 128 gemm2

__device__ __forceinline__ uint32_t smem_u32(const void* p) {
    uint32_t a;
    asm("{ .reg .u64 t; cvta.to.shared.u64 t, %1; cvt.u32.u64 %0, t; }" : "=r"(a) : "l"(p));
    return a;
}
__device__ __forceinline__ float rna(float v) {
    uint32_t r;
    asm("cvt.rna.tf32.f32 %0, %1;" : "=r"(r) : "f"(v));
    return __uint_as_float(r);
}
__device__ __forceinline__ uint32_t lds32(uint32_t a) {
    uint32_t v;
    asm volatile("ld.shared.b32 %0, [%1];" : "=r"(v) : "r"(a));
    return v;
}
__device__ __forceinline__ void cpa16(uint32_t dst, const void* src) {
    asm volatile("cp.async.cg.shared.global [%0], [%1], 16;" :: "r"(dst), "l"(src) : "memory");
}
__device__ __forceinline__ void cpa_commit() {
    asm volatile("cp.async.commit_group;" ::: "memory");
}
__device__ __forceinline__ void cpa_wait4() {
    asm volatile("cp.async.wait_group 4;" ::: "memory");
}
__device__ __forceinline__ int ld_acq(const int* p) {
    int v;
    asm volatile("ld.acquire.gpu.global.b32 %0, [%1];" : "=r"(v) : "l"(p) : "memory");
    return v;
}
__device__ __forceinline__ void mma8(float* c, const uint32_t* a, const uint32_t* b) {
    asm volatile(
        "mma.sync.aligned.m16n8k8.row.col.f32.tf32.tf32.f32 "
        "{%0,%1,%2,%3}, {%4,%5,%6,%7}, {%8,%9}, {%0,%1,%2,%3};"
        : "+f"(c[0]), "+f"(c[1]), "+f"(c[2]), "+f"(c[3])
        : "r"(a[0]), "r"(a[1]), "r"(a[2]), "r"(a[3]), "r"(b[0]), "r"(b[1]));
}

__global__ void zero_flags() { if (threadIdx.x < SQ) g_done[threadIdx.x] = 0; }

// One launch, 640 blocks x 512 threads. kind1: H[s] tile (BN=512). kind2: gemm2+LN.
__global__ __launch_bounds__(512, 1) void ffn_fused(
    const float* __restrict__ W1, const float* __restrict__ b1,
    const float* __restrict__ W2, const float* __restrict__ b2,
    const float* __restrict__ x, const float* __restrict__ gamma,
    const float* __restrict__ beta, float* __restrict__ outp)
{
    // ---- static schedule: groups of 5 = 4x g1(s) + 1x g2(s-LAG) ----
    const int bid = blockIdx.x;
    int kind, s, n0 = 0;
    if (bid < 4 * LAG) {
        kind = 1; s = bid >> 2; n0 = (bid & 3) * 512;
    } else if (bid < NBLK - LAG) {
        const int j = bid - 4 * LAG, grp = j / 5 + LAG, r = j - (j / 5) * 5;
        if (r < 4) { kind = 1; s = grp; n0 = r * 512; }
        else       { kind = 2; s = grp - LAG; }
    } else {
        kind = 2; s = (SQ - LAG) + (bid - (NBLK - LAG));
    }

    const int K    = (kind == 1) ? EE : FF;
    const int NSTR = (kind == 1) ? FF : EE;
    const int NCH  = K / 16;

    extern __shared__ char smem[];
    const uint32_t sb = smem_u32(smem);
    const int tid = threadIdx.x, wid = tid >> 5, lid = tid & 31;
    const uint32_t g = lid >> 2, tig = lid & 3;

    const float* Ab = (kind == 1) ? x + (size_t)s * EE : g_H + (size_t)s * BB * FF;
    const size_t Ar = (kind == 1) ? (size_t)SQ * EE : (size_t)FF;
    const float* Wb = ((kind == 1) ? W1 : W2) + (size_t)s * ((size_t)EE * FF) + n0;
    const float* bias = (kind == 1) ? b1 : b2;

    if (kind == 2) {                    // wait for all 4 producer blocks of s
        if (tid == 0) while (ld_acq(&g_done[s]) < 4) {}
        __syncthreads();
    }

    const int arow = tid >> 2, ac4 = tid & 3;   // A: tid<128, 32 rows x 4 f4
    const int br0 = tid >> 7, bc4 = tid & 127;  // B: 16 rows x 128 f4, 4/thread

    auto issue = [&](int c) {
        const uint32_t stg = sb + (c % NSTAGE) * STG;
        const int k0 = c * 16;
        if (tid < 128)
            cpa16(stg + arow * 80 + ac4 * 16, Ab + (size_t)arow * Ar + k0 + ac4 * 4);
#pragma unroll
        for (int i = 0; i < 4; i++) {
            const int r = br0 + i * 4;
            cpa16(stg + 2560 + r * 2048 + (((bc4 + 2 * (r & 3)) & 127) << 4),
                  Wb + (size_t)(k0 + r) * NSTR + bc4 * 4);
        }
        cpa_commit();
    };
    issue(0); issue(1); issue(2); issue(3); issue(4);

    float acc[2][4][4];
#pragma unroll
    for (int i = 0; i < 2; i++)
#pragma unroll
        for (int j = 0; j < 4; j++)
#pragma unroll
            for (int q = 0; q < 4; q++) acc[i][j][q] = 0.0f;

    uint32_t bcol[4];
#pragma unroll
    for (int nt = 0; nt < 4; nt++) {
        const uint32_t n = wid * 32 + nt * 8 + g;
        bcol[nt] = ((((n >> 2) + 2 * tig) & 127) << 4) + (n & 3) * 4;
    }

#pragma unroll 1
    for (int c = 0; c < NCH; c++) {
        cpa_wait4();
        __syncthreads();
        if (c + 5 < NCH) issue(c + 5); else cpa_commit();
        const uint32_t Aa = sb + (c % NSTAGE) * STG;
        const uint32_t Ba = Aa + 2560;
#pragma unroll
        for (int ks = 0; ks < 2; ks++) {
            uint32_t a[2][4], b[4][2];
#pragma unroll
            for (int mt = 0; mt < 2; mt++) {
                const uint32_t base = Aa + (mt * 16 + g) * 80 + (ks * 8 + tig) * 4;
                a[mt][0] = lds32(base);
                a[mt][1] = lds32(base + 8 * 80);
                a[mt][2] = lds32(base + 16);
                a[mt][3] = lds32(base + 8 * 80 + 16);
#pragma unroll
                for (int q = 0; q < 4; q++)   // real rounding for x, identity for H
                    a[mt][q] = __float_as_uint(rna(__uint_as_float(a[mt][q])));
            }
            const uint32_t kk = ks * 8 + tig;
#pragma unroll
            for (int nt = 0; nt < 4; nt++) {
                b[nt][0] = lds32(Ba + kk * 2048 + bcol[nt]);
                b[nt][1] = lds32(Ba + (kk + 4) * 2048 + bcol[nt]);
            }
#pragma unroll
            for (int mt = 0; mt < 2; mt++)
#pragma unroll
                for (int nt = 0; nt < 4; nt++) mma8(acc[mt][nt], a[mt], b[nt]);
        }
    }

    if (kind == 1) {
        // epilogue: H = rna(acc + b1); then release flag
#pragma unroll
        for (int mt = 0; mt < 2; mt++)
#pragma unroll
            for (int half = 0; half < 2; half++) {
                const int m = mt * 16 + g + half * 8;
#pragma unroll
                for (int nt = 0; nt < 4; nt++) {
                    const int n = n0 + wid * 32 + nt * 8 + 2 * tig;
                    float2 o = make_float2(
                        rna(acc[mt][nt][half * 2]     + b1[(size_t)s * FF + n]),
                        rna(acc[mt][nt][half * 2 + 1] + b1[(size_t)s * FF + n + 1]));
                    *reinterpret_cast<float2*>(g_H + ((size_t)s * BB + m) * FF + n) = o;
                }
            }
        __threadfence();
        __syncthreads();
        if (tid == 0) {
            int one = 1, dummy;
            asm volatile("atom.add.release.gpu.global.s32 %0, [%1], %2;"
                         : "=r"(dummy) : "l"(&g_done[s]), "r"(one) : "memory");
        }
        return;
    }

    // ---- kind 2: y = acc + b2 + x, block LN over e, write out ----
#pragma unroll
    for (int mt = 0; mt < 2; mt++)
#pragma unroll
        for (int half = 0; half < 2; half++) {
            const int m = mt * 16 + g + half * 8;
#pragma unroll
            for (int nt = 0; nt < 4; nt++) {
                const int n = wid * 32 + nt * 8 + 2 * tig;
                const float2 xr = *reinterpret_cast<const float2*>(
                    x + ((size_t)m * SQ + s) * EE + n);
                acc[mt][nt][half * 2]     += bias[(size_t)s * EE + n] + xr.x;
                acc[mt][nt][half * 2 + 1] += bias[(size_t)s * EE + n + 1] + xr.y;
            }
        }

    float* redS = reinterpret_cast<float*>(smem);
    float* redQ = redS + 512;
    float* muS  = redQ + 512;
    float* invS = muS + 32;
    __syncthreads();
#pragma unroll
    for (int mt = 0; mt < 2; mt++)
#pragma unroll
        for (int half = 0; half < 2; half++) {
            float s1 = 0.f, s2 = 0.f;
#pragma unroll
            for (int nt = 0; nt < 4; nt++) {
                const float v0 = acc[mt][nt][half * 2], v1 = acc[mt][nt][half * 2 + 1];
                s1 += v0 + v1;
                s2 += v0 * v0 + v1 * v1;
            }
            s1 += __shfl_xor_sync(0xffffffffu, s1, 1);
            s1 += __shfl_xor_sync(0xffffffffu, s1, 2);
            s2 += __shfl_xor_sync(0xffffffffu, s2, 1);
            s2 += __shfl_xor_sync(0xffffffffu, s2, 2);
            if (tig == 0) {
                const int m = mt * 16 + half * 8 + g;
                redS[wid * 32 + m] = s1;
                redQ[wid * 32 + m] = s2;
            }
        }
    __syncthreads();
    if (tid < 32) {
        float s1 = 0.f, s2 = 0.f;
#pragma unroll
        for (int w = 0; w < 16; w++) { s1 += redS[w * 32 + tid]; s2 += redQ[w * 32 + tid]; }
        const float mu = s1 * (1.0f / EE);
        muS[tid]  = mu;
        invS[tid] = rsqrtf(s2 * (1.0f / EE) - mu * mu + 1e-5f);
    }
    __syncthreads();
#pragma unroll
    for (int mt = 0; mt < 2; mt++)
#pragma unroll
        for (int half = 0; half < 2; half++) {
            const int m = mt * 16 + g + half * 8;
            const float mu = muS[m], inv = invS[m];
#pragma unroll
            for (int nt = 0; nt < 4; nt++) {
                const int n = wid * 32 + nt * 8 + 2 * tig;
                const float2 ga = *reinterpret_cast<const float2*>(gamma + n);
                const float2 be = *reinterpret_cast<const float2*>(beta + n);
                float2 o;
                o.x = (acc[mt][nt][half * 2]     - mu) * inv * ga.x + be.x;
                o.y = (acc[mt][nt][half * 2 + 1] - mu) * inv * ga.y + be.y;
                *reinterpret_cast<float2*>(outp + ((size_t)m * SQ + s) * EE + n) = o;
            }
        }
}

extern "C" void kernel_launch(void* const* d_in, const int* in_sizes, int n_in,
                              void* d_out, int out_size)
{
    const float* x  = (const float*)d_in[0];
    const float* W1 = (const float*)d_in[1];
    const float* b1 = (const float*)d_in[2];
    const float* W2 = (const float*)d_in[3];
    const float* b2 = (const float*)d_in[4];
    const float* ga = (const float*)d_in[5];
    const float* be = (const float*)d_in[6];
    float* out = (float*)d_out;

    static int init = 0;
    if (!init) {
        cudaFuncSetAttribute(ffn_fused, cudaFuncAttributeMaxDynamicSharedMemorySize, SMB);
        cudaFuncSetAttribute(ffn_fused, cudaFuncAttributePreferredSharedMemoryCarveout, 100);
        init = 1;
    }

    zero_flags<<<1, 128>>>();
    ffn_fused<<<NBLK, 512, SMB>>>(W1, b1, W2, b2, x, ga, be, out);
}

// round 14
// speedup vs baseline: 2.1299x; 2.1299x over previous
#include <cuda_runtime.h>
#include <cstdint>

#define BB 32
#define SQ 128
#define EE 512
#define FF 2048

__device__ float g_H[(size_t)SQ * BB * FF];  // [s][b][f]

#define STG1 18944            // A 32x80=2560 + B 16x1024=16384
#define SMB1 (4 * STG1)
#define STG2 35328            // A 32x80=2560 + B 16x2048=32768
#define NS2  5
#define SMB2 (NS2 * STG2)     // 176640

__device__ __forceinline__ uint32_t smem_u32(const void* p) {
    uint32_t a;
    asm("{ .reg .u64 t; cvta.to.shared.u64 t, %1; cvt.u32.u64 %0, t; }" : "=r"(a) : "l"(p));
    return a;
}
__device__ __forceinline__ float rna(float v) {
    uint32_t r;
    asm("cvt.rna.tf32.f32 %0, %1;" : "=r"(r) : "f"(v));
    return __uint_as_float(r);
}
__device__ __forceinline__ uint32_t lds32(uint32_t a) {
    uint32_t v;
    asm volatile("ld.shared.b32 %0, [%1];" : "=r"(v) : "r"(a));
    return v;
}
__device__ __forceinline__ void cpa16(uint32_t dst, const void* src) {
    asm volatile("cp.async.cg.shared.global [%0], [%1], 16;" :: "r"(dst), "l"(src) : "memory");
}
__device__ __forceinline__ void cpa_commit() {
    asm volatile("cp.async.commit_group;" ::: "memory");
}
__device__ __forceinline__ void cpa_wait2() {
    asm volatile("cp.async.wait_group 2;" ::: "memory");
}
__device__ __forceinline__ void cpa_wait3() {
    asm volatile("cp.async.wait_group 3;" ::: "memory");
}
__device__ __forceinline__ void mma8(float* c, const uint32_t* a, const uint32_t* b) {
    asm volatile(
        "mma.sync.aligned.m16n8k8.row.col.f32.tf32.tf32.f32 "
        "{%0,%1,%2,%3}, {%4,%5,%6,%7}, {%8,%9}, {%0,%1,%2,%3};"
        : "+f"(c[0]), "+f"(c[1]), "+f"(c[2]), "+f"(c[3])
        : "r"(a[0]), "r"(a[1]), "r"(a[2]), "r"(a[3]), "r"(b[0]), "r"(b[1]));
}

// ---------------- GEMM1: H[s][b][f] = rna(x[:,s,:]) @ W1[s] + b1[s] ----------------
__global__ __launch_bounds__(256, 3) void ffn1(
    const float* __restrict__ W1, const float* __restrict__ b1,
    const float* __restrict__ x)
{
    constexpr int NCH = EE / 16;
    extern __shared__ char smem[];
    const uint32_t sb = smem_u32(smem);
    const int tid = threadIdx.x, wid = tid >> 5, lid = tid & 31;
    const int s = blockIdx.y, n0 = blockIdx.x * 256;
    const uint32_t g = lid >> 2, tig = lid & 3;

    const float* Ab = x + (size_t)s * EE;
    const float* Wb = W1 + (size_t)s * ((size_t)EE * FF) + n0;
    const int arow = tid >> 2, ac4 = tid & 3;
    const int br0 = tid >> 6, bc4 = tid & 63;

    auto issue = [&](int c) {
        const uint32_t stg = sb + (c & 3) * STG1;
        const int k0 = c * 16;
        if (tid < 128)
            cpa16(stg + arow * 80 + ac4 * 16,
                  Ab + (size_t)arow * SQ * EE + k0 + ac4 * 4);
#pragma unroll
        for (int i = 0; i < 4; i++) {
            const int r = br0 + i * 4;
            cpa16(stg + 2560 + r * 1024 + (((bc4 + 2 * (r & 3)) & 63) << 4),
                  Wb + (size_t)(k0 + r) * FF + bc4 * 4);
        }
        cpa_commit();
    };
    issue(0); issue(1); issue(2);

    float acc[2][4][4];
#pragma unroll
    for (int i = 0; i < 2; i++)
#pragma unroll
        for (int j = 0; j < 4; j++)
#pragma unroll
            for (int q = 0; q < 4; q++) acc[i][j][q] = 0.0f;

    uint32_t bcol[4];
#pragma unroll
    for (int nt = 0; nt < 4; nt++) {
        const uint32_t n = wid * 32 + nt * 8 + g;
        bcol[nt] = ((((n >> 2) + 2 * tig) & 63) << 4) + (n & 3) * 4;
    }

#pragma unroll 1
    for (int c = 0; c < NCH; c++) {
        cpa_wait2();
        __syncthreads();
        if (c + 3 < NCH) issue(c + 3); else cpa_commit();
        const uint32_t Aa = sb + (c & 3) * STG1;
        const uint32_t Ba = Aa + 2560;
#pragma unroll
        for (int ks = 0; ks < 2; ks++) {
            uint32_t a[2][4], b[4][2];
#pragma unroll
            for (int mt = 0; mt < 2; mt++) {
                const uint32_t base = Aa + (mt * 16 + g) * 80 + (ks * 8 + tig) * 4;
                a[mt][0] = lds32(base);
                a[mt][1] = lds32(base + 8 * 80);
                a[mt][2] = lds32(base + 16);
                a[mt][3] = lds32(base + 8 * 80 + 16);
#pragma unroll
                for (int q = 0; q < 4; q++)
                    a[mt][q] = __float_as_uint(rna(__uint_as_float(a[mt][q])));
            }
            const uint32_t kk = ks * 8 + tig;
#pragma unroll
            for (int nt = 0; nt < 4; nt++) {
                b[nt][0] = lds32(Ba + kk * 1024 + bcol[nt]);
                b[nt][1] = lds32(Ba + (kk + 4) * 1024 + bcol[nt]);
            }
#pragma unroll
            for (int mt = 0; mt < 2; mt++)
#pragma unroll
                for (int nt = 0; nt < 4; nt++) mma8(acc[mt][nt], a[mt], b[nt]);
        }
    }

#pragma unroll
    for (int mt = 0; mt < 2; mt++)
#pragma unroll
        for (int half = 0; half < 2; half++) {
            const int m = mt * 16 + g + half * 8;
#pragma unroll
            for (int nt = 0; nt < 4; nt++) {
                const int n = n0 + wid * 32 + nt * 8 + 2 * tig;
                const float b0 = b1[(size_t)s * FF + n];
                const float b1v = b1[(size_t)s * FF + n + 1];
                float2 o = make_float2(rna(acc[mt][nt][half * 2] + b0),
                                       rna(acc[mt][nt][half * 2 + 1] + b1v));
                *reinterpret_cast<float2*>(g_H + ((size_t)s * BB + m) * FF + n) = o;
            }
        }
}

// ------- GEMM2 + LN: out = LN(H[s] @ W2[s] + b2[s] + x), one block per s -------
__global__ __launch_bounds__(512, 1) void ffn2_ln(
    const float* __restrict__ W2, const float* __restrict__ b2,
    const float* __restrict__ x, const float* __restrict__ gamma,
    const float* __restrict__ beta, float* __restrict__ outp)
{
    constexpr int NCH = FF / 16;
    extern __shared__ char smem[];
    const uint32_t sb = smem_u32(smem);
    const int tid = threadIdx.x, wid = tid >> 5, lid = tid & 31;
    const int s = blockIdx.x;
    const uint32_t g = lid >> 2, tig = lid & 3;

    const float* Ab = g_H + (size_t)s * BB * FF;
    const float* Wb = W2 + (size_t)s * ((size_t)FF * EE);
    const int arow = tid >> 2, ac4 = tid & 3;
    const int br0 = tid >> 7, bc4 = tid & 127;

    auto issue = [&](int c) {
        const uint32_t stg = sb + (c % NS2) * STG2;
        const int k0 = c * 16;
        if (tid < 128)
            cpa16(stg + arow * 80 + ac4 * 16, Ab + (size_t)arow * FF + k0 + ac4 * 4);
#pragma unroll
        for (int i = 0; i < 4; i++) {
            const int r = br0 + i * 4;
            cpa16(stg + 2560 + r * 2048 + (((bc4 + 2 * (r & 3)) & 127) << 4),
                  Wb + (size_t)(k0 + r) * EE + bc4 * 4);
        }
        cpa_commit();
    };
    issue(0); issue(1); issue(2); issue(3);

    float acc[2][4][4];
#pragma unroll
    for (int i = 0; i < 2; i++)
#pragma unroll
        for (int j = 0; j < 4; j++)
#pragma unroll
            for (int q = 0; q < 4; q++) acc[i][j][q] = 0.0f;

    uint32_t bcol[4];
#pragma unroll
    for (int nt = 0; nt < 4; nt++) {
        const uint32_t n = wid * 32 + nt * 8 + g;
        bcol[nt] = ((((n >> 2) + 2 * tig) & 127) << 4) + (n & 3) * 4;
    }

#pragma unroll 1
    for (int c = 0; c < NCH; c++) {
        cpa_wait3();
        __syncthreads();
        if (c + 4 < NCH) issue(c + 4); else cpa_commit();
        const uint32_t Aa = sb + (c % NS2) * STG2;
        const uint32_t Ba = Aa + 2560;
#pragma unroll
        for (int ks = 0; ks < 2; ks++) {
            uint32_t a[2][4], b[4][2];
#pragma unroll
            for (int mt = 0; mt < 2; mt++) {
                const uint32_t base = Aa + (mt * 16 + g) * 80 + (ks * 8 + tig) * 4;
                a[mt][0] = lds32(base);
                a[mt][1] = lds32(base + 8 * 80);
                a[mt][2] = lds32(base + 16);
                a[mt][3] = lds32(base + 8 * 80 + 16);
            }
            const uint32_t kk = ks * 8 + tig;
#pragma unroll
            for (int nt = 0; nt < 4; nt++) {
                b[nt][0] = lds32(Ba + kk * 2048 + bcol[nt]);
                b[nt][1] = lds32(Ba + (kk + 4) * 2048 + bcol[nt]);
            }
#pragma unroll
            for (int mt = 0; mt < 2; mt++)
#pragma unroll
                for (int nt = 0; nt < 4; nt++) mma8(acc[mt][nt], a[mt], b[nt]);
        }
    }

    // y = acc + b2 + x, then block LN over e (512)
#pragma unroll
    for (int mt = 0; mt < 2; mt++)
#pragma unroll
        for (int half = 0; half < 2; half++) {
            const int m = mt * 16 + g + half * 8;
#pragma unroll
            for (int nt = 0; nt < 4; nt++) {
                const int n = wid * 32 + nt * 8 + 2 * tig;
                const float2 xr = *reinterpret_cast<const float2*>(
                    x + ((size_t)m * SQ + s) * EE + n);
                acc[mt][nt][half * 2]     += b2[(size_t)s * EE + n] + xr.x;
                acc[mt][nt][half * 2 + 1] += b2[(size_t)s * EE + n + 1] + xr.y;
            }
        }

    float* redS = reinterpret_cast<float*>(smem);
    float* redQ = redS + 512;
    float* muS  = redQ + 512;
    float* invS = muS + 32;
    __syncthreads();
#pragma unroll
    for (int mt = 0; mt < 2; mt++)
#pragma unroll
        for (int half = 0; half < 2; half++) {
            float s1 = 0.f, s2 = 0.f;
#pragma unroll
            for (int nt = 0; nt < 4; nt++) {
                const float v0 = acc[mt][nt][half * 2], v1 = acc[mt][nt][half * 2 + 1];
                s1 += v0 + v1;
                s2 += v0 * v0 + v1 * v1;
            }
            s1 += __shfl_xor_sync(0xffffffffu, s1, 1);
            s1 += __shfl_xor_sync(0xffffffffu, s1, 2);
            s2 += __shfl_xor_sync(0xffffffffu, s2, 1);
            s2 += __shfl_xor_sync(0xffffffffu, s2, 2);
            if (tig == 0) {
                const int m = mt * 16 + half * 8 + g;
                redS[wid * 32 + m] = s1;
                redQ[wid * 32 + m] = s2;
            }
        }
    __syncthreads();
    if (tid < 32) {
        float s1 = 0.f, s2 = 0.f;
#pragma unroll
        for (int w = 0; w < 16; w++) { s1 += redS[w * 32 + tid]; s2 += redQ[w * 32 + tid]; }
        const float mu = s1 * (1.0f / EE);
        muS[tid]  = mu;
        invS[tid] = rsqrtf(s2 * (1.0f / EE) - mu * mu + 1e-5f);
    }
    __syncthreads();
#pragma unroll
    for (int mt = 0; mt < 2; mt++)
#pragma unroll
        for (int half = 0; half < 2; half++) {
            const int m = mt * 16 + g + half * 8;
            const float mu = muS[m], inv = invS[m];
#pragma unroll
            for (int nt = 0; nt < 4; nt++) {
                const int n = wid * 32 + nt * 8 + 2 * tig;
                const float2 ga = *reinterpret_cast<const float2*>(gamma + n);
                const float2 be = *reinterpret_cast<const float2*>(beta + n);
                float2 o;
                o.x = (acc[mt][nt][half * 2]     - mu) * inv * ga.x + be.x;
                o.y = (acc[mt][nt][half * 2 + 1] - mu) * inv * ga.y + be.y;
                *reinterpret_cast<float2*>(outp + ((size_t)m * SQ + s) * EE + n) = o;
            }
        }
}

extern "C" void kernel_launch(void* const* d_in, const int* in_sizes, int n_in,
                              void* d_out, int out_size)
{
    const float* x  = (const float*)d_in[0];
    const float* W1 = (const float*)d_in[1];
    const float* b1 = (const float*)d_in[2];
    const float* W2 = (const float*)d_in[3];
    const float* b2 = (const float*)d_in[4];
    const float* ga = (const float*)d_in[5];
    const float* be = (const float*)d_in[6];
    float* out = (float*)d_out;

    static int init = 0;
    if (!init) {
        cudaFuncSetAttribute(ffn1, cudaFuncAttributeMaxDynamicSharedMemorySize, SMB1);
        cudaFuncSetAttribute(ffn2_ln, cudaFuncAttributeMaxDynamicSharedMemorySize, SMB2);
        cudaFuncSetAttribute(ffn1, cudaFuncAttributePreferredSharedMemoryCarveout, 100);
        cudaFuncSetAttribute(ffn2_ln, cudaFuncAttributePreferredSharedMemoryCarveout, 100);
        init = 1;
    }

    ffn1<<<dim3(FF / 256, SQ), 256, SMB1>>>(W1, b1, x);
    ffn2_ln<<<SQ, 512, SMB2>>>(W2, b2, x, ga, be, out);
}